// round 10
// baseline (speedup 1.0000x reference)
#include <cuda_runtime.h>
#include <math.h>

#define NB 16384
#define ND 16
#define KNN 25
#define LAMBDA_TSA 0.1f
#define FULLM 0xffffffffu
#define FLTMAX 3.402823466e+38f

#define WPB 8                 // warps per block; 1 query per warp
#define CTILE 128             // candidates per smem tile (64 pair-rows)
#define PSTR 36               // pair-row stride in floats (32 data + 2 sq + 2 pad)

// packed f32x2 helpers
#define FMA2(d, a, b, c) \
    asm("fma.rn.f32x2 %0, %1, %2, %3;" : "=l"(d) : "l"(a), "l"(b), "l"(c))
#define PACK2(out, lo, hi) \
    asm("mov.b64 %0, {%1, %2};" : "=l"(out) : "f"(lo), "f"(hi))
#define UNPACK2(lo, hi, in) \
    asm("mov.b64 {%0, %1}, %2;" : "=f"(lo), "=f"(hi) : "l"(in))

// ---------------- device scratch (no allocations allowed) ----------------
__device__ float g_sq[NB];
__device__ int   g_nbrs[NB][KNN];
__device__ float g_acc_recon;
__device__ float g_acc_tsa;

// ---------------- kernel 1: squared norms + zero accumulators ----------------
__global__ void k_setup(const float* __restrict__ raw) {
    int i = blockIdx.x * blockDim.x + threadIdx.x;
    if (i < NB) {
        const float4* r4 = reinterpret_cast<const float4*>(raw + (size_t)i * ND);
        float s = 0.f;
#pragma unroll
        for (int j = 0; j < 4; ++j) {
            float4 v = r4[j];
            s = fmaf(v.x, v.x, s); s = fmaf(v.y, v.y, s);
            s = fmaf(v.z, v.z, s); s = fmaf(v.w, v.w, s);
        }
        g_sq[i] = s;
    }
    if (i == 0) { g_acc_recon = 0.f; g_acc_tsa = 0.f; }
}

// ---------------- kernel 2: recon MSE sum ----------------
__global__ void k_recon(const float* __restrict__ o, const float* __restrict__ t) {
    const float4* o4 = reinterpret_cast<const float4*>(o);
    const float4* t4 = reinterpret_cast<const float4*>(t);
    const int n4 = NB * ND / 4;
    float s = 0.f;
    for (int idx = blockIdx.x * blockDim.x + threadIdx.x; idx < n4;
         idx += gridDim.x * blockDim.x) {
        float4 a = o4[idx], b = t4[idx];
        float dx = a.x - b.x, dy = a.y - b.y, dz = a.z - b.z, dw = a.w - b.w;
        s = fmaf(dx, dx, s); s = fmaf(dy, dy, s);
        s = fmaf(dz, dz, s); s = fmaf(dw, dw, s);
    }
#pragma unroll
    for (int off = 16; off; off >>= 1) s += __shfl_xor_sync(FULLM, s, off);
    __shared__ float ws[8];
    int lane = threadIdx.x & 31, wid = threadIdx.x >> 5;
    if (lane == 0) ws[wid] = s;
    __syncthreads();
    if (threadIdx.x == 0) {
        float tot = 0.f;
#pragma unroll
        for (int k = 0; k < 8; ++k) tot += ws[k];
        atomicAdd(&g_acc_recon, tot);
    }
}

// combined max+argmax over list lanes (<KNN); all lanes get the result
__device__ __forceinline__ void maxreduce25(float v, int lane, float& outv, int& outl) {
    float mv = (lane < KNN) ? v : -FLTMAX;
    int   ml = lane;
#pragma unroll
    for (int off = 16; off; off >>= 1) {
        float ov = __shfl_xor_sync(FULLM, mv, off);
        int   ol = __shfl_xor_sync(FULLM, ml, off);
        if (ov > mv || (ov == mv && ol < ml)) { mv = ov; ml = ol; }
    }
    outv = mv; outl = ml;
}

// ---------------- kernel 3: fused distance GEMM + warp-cooperative top-25 ----
// One warp = one query. Candidates packed in PAIRS in smem: row p holds
// (cA[2k],cB[2k],cA[2k+1],cB[2k+1]) quads (+ both sq) so one LDS.128 yields
// two ready-packed f32x2 operands for fma.rn.f32x2. Tile fill uses paired
// float2 LDGs and a single STS.128 per quad (no scalar-store storm).
// Double-buffered smem, 1 sync/tile. Distributed top-25 with (tau,mlane).
__global__ void __launch_bounds__(256) k_knn(const float* __restrict__ raw) {
    __shared__ float Cs[2][(CTILE / 2) * PSTR];

    const int tid  = threadIdx.x;
    const int lane = tid & 31;
    const int w    = tid >> 5;
    const int q    = blockIdx.x * WPB + w;

    // tile-fill tasks: f in {tid, tid+256}; p = f>>3 (pair), k = f&7 (dim pair)
    const int p0 = tid >> 3,          k0 = tid & 7;
    const int p1 = (tid + 256) >> 3,  k1 = (tid + 256) & 7;

    // splat-packed query
    unsigned long long qs[ND];
#pragma unroll
    for (int d = 0; d < ND; ++d) {
        float qv = __ldg(raw + (size_t)q * ND + d);
        PACK2(qs[d], qv, qv);
    }
    unsigned long long m2;
    PACK2(m2, -2.f, -2.f);

    float lv = FLTMAX; int li = 0; float tau = FLTMAX; int mlane = 0;

    const float2* raw2 = reinterpret_cast<const float2*>(raw);
    const float2* sq2p = reinterpret_cast<const float2*>(g_sq);

    // prefetch tile 0
    float2 pa0 = raw2[(size_t)(2 * p0) * 8 + k0];
    float2 pb0 = raw2[(size_t)(2 * p0 + 1) * 8 + k0];
    float2 pa1 = raw2[(size_t)(2 * p1) * 8 + k1];
    float2 pb1 = raw2[(size_t)(2 * p1 + 1) * 8 + k1];
    float2 psq = (tid < 64) ? sq2p[tid] : make_float2(0.f, 0.f);
    {
        *reinterpret_cast<float4*>(&Cs[0][p0 * PSTR + 4 * k0]) =
            make_float4(pa0.x, pb0.x, pa0.y, pb0.y);
        *reinterpret_cast<float4*>(&Cs[0][p1 * PSTR + 4 * k1]) =
            make_float4(pa1.x, pb1.x, pa1.y, pb1.y);
        if (tid < 64)
            *reinterpret_cast<float2*>(&Cs[0][tid * PSTR + 32]) = psq;
    }
    __syncthreads();

    const int NT = NB / CTILE;
    for (int t = 0; t < NT; ++t) {
        const int cbase = t * CTILE;
        const bool more = (t + 1 < NT);
        if (more) {   // prefetch next tile (LDG latency overlaps compute)
            const size_t nb2 = (size_t)(cbase + CTILE) * 8;   // float2 units
            pa0 = raw2[nb2 + (size_t)(2 * p0) * 8 + k0];
            pb0 = raw2[nb2 + (size_t)(2 * p0 + 1) * 8 + k0];
            pa1 = raw2[nb2 + (size_t)(2 * p1) * 8 + k1];
            pb1 = raw2[nb2 + (size_t)(2 * p1 + 1) * 8 + k1];
            if (tid < 64) psq = sq2p[(cbase + CTILE) / 2 + tid];
        }
        const float* buf = Cs[t & 1];

#pragma unroll
        for (int g = 0; g < CTILE / 64; ++g) {
            const int p   = g * 32 + lane;          // pair-row index
            const int cgA = cbase + 2 * p;          // candidate A (even)
            const float* rowp = buf + p * PSTR;

            unsigned long long acc;
            PACK2(acc, 0.f, 0.f);
#pragma unroll
            for (int k = 0; k < 8; ++k) {
                ulonglong2 u = *reinterpret_cast<const ulonglong2*>(rowp + 4 * k);
                FMA2(acc, qs[2 * k], u.x, acc);
                FMA2(acc, qs[2 * k + 1], u.y, acc);
            }
            unsigned long long sq2 =
                *reinterpret_cast<const unsigned long long*>(rowp + 32);
            unsigned long long d2p;
            FMA2(d2p, m2, acc, sq2);
            float dA, dB;
            UNPACK2(dA, dB, d2p);

            bool pA = (dA < tau) & (cgA != q);
            bool pB = (dB < tau) & (cgA + 1 != q);
            if (__ballot_sync(FULLM, pA | pB)) {
                unsigned mA = __ballot_sync(FULLM, pA);
                unsigned mB = __ballot_sync(FULLM, pB);
                while (mA) {
                    int src = __ffs(mA) - 1; mA &= mA - 1;
                    float dv = __shfl_sync(FULLM, dA, src);
                    int   ci = __shfl_sync(FULLM, cgA, src);
                    if (dv < tau) {
                        if (lane == mlane) { lv = dv; li = ci; }
                        maxreduce25(lv, lane, tau, mlane);
                    }
                }
                while (mB) {
                    int src = __ffs(mB) - 1; mB &= mB - 1;
                    float dv = __shfl_sync(FULLM, dB, src);
                    int   ci = __shfl_sync(FULLM, cgA, src) + 1;
                    if (dv < tau) {
                        if (lane == mlane) { lv = dv; li = ci; }
                        maxreduce25(lv, lane, tau, mlane);
                    }
                }
            }
        }

        if (more) {   // store next tile into the other buffer
            float* nbuf = Cs[(t + 1) & 1];
            *reinterpret_cast<float4*>(&nbuf[p0 * PSTR + 4 * k0]) =
                make_float4(pa0.x, pb0.x, pa0.y, pb0.y);
            *reinterpret_cast<float4*>(&nbuf[p1 * PSTR + 4 * k1]) =
                make_float4(pa1.x, pb1.x, pa1.y, pb1.y);
            if (tid < 64)
                *reinterpret_cast<float2*>(&nbuf[tid * PSTR + 32]) = psq;
        }
        __syncthreads();
    }

    if (lane < KNN) g_nbrs[q][lane] = li;
}

// ---------------- kernel 4: per-point TSA term (warp per point) --------------
// P=1: sum((Pz-Px)^2) = 2 - 2*(u.v)^2, u,v unit top-eigenvectors.
// Eigvec by 7 repeated squarings (A^128), symmetric row-row matmul via
// LDS.128 on stride-20 rows; single mid-way max-diag rescale.
#define TSA_WPB 8
#define TSTR 20
__global__ void __launch_bounds__(256) k_tsa(const float* __restrict__ latent,
                                             const float* __restrict__ raw) {
    __shared__ float s_pts[TSA_WPB][KNN][ND];
    __shared__ float s_A[TSA_WPB][16 * TSTR];
    __shared__ float s_B[TSA_WPB][16 * TSTR];
    __shared__ float s_u[TSA_WPB][16];
    __shared__ float s_v[TSA_WPB][16];
    __shared__ float s_mu[TSA_WPB][16];
    __shared__ int   s_nb[TSA_WPB][KNN];

    const int w = threadIdx.x >> 5, lane = threadIdx.x & 31;
    const int i = blockIdx.x * TSA_WPB + w;
    const int ra   = lane >> 1;     // row a for matmul
    const int bpar = lane & 1;      // b parity

    if (lane < KNN) s_nb[w][lane] = g_nbrs[i][lane];
    __syncwarp();

    for (int p = 0; p < 2; ++p) {
        const float* src = p ? raw : latent;
        float* uvec = p ? s_v[w] : s_u[w];

        for (int idx = lane; idx < KNN * ND; idx += 32) {
            int k = idx >> 4, d = idx & 15;
            s_pts[w][k][d] = src[(size_t)s_nb[w][k] * ND + d];
        }
        __syncwarp();
        if (lane < 16) {
            float m = 0.f;
#pragma unroll
            for (int k = 0; k < KNN; ++k) m += s_pts[w][k][lane];
            s_mu[w][lane] = m * (1.f / KNN);
        }
        __syncwarp();
        for (int idx = lane; idx < KNN * ND; idx += 32) {
            int k = idx >> 4, d = idx & 15;
            s_pts[w][k][d] -= s_mu[w][d];
        }
        __syncwarp();
        // covariance (unnormalized; scale-invariant for eigvec)
        for (int e = lane; e < 256; e += 32) {
            int a = e >> 4, b = e & 15;
            float s = 0.f;
#pragma unroll
            for (int k = 0; k < KNN; ++k) s = fmaf(s_pts[w][k][a], s_pts[w][k][b], s);
            s_A[w][a * TSTR + b] = s;
        }
        __syncwarp();

        float* Ain = s_A[w];
        float* Aou = s_B[w];
#pragma unroll 1
        for (int sq = 0; sq < 7; ++sq) {
            // C[a][b] = row_a . row_b  (A symmetric)
            const float4 A0 = *reinterpret_cast<const float4*>(Ain + ra * TSTR);
            const float4 A1 = *reinterpret_cast<const float4*>(Ain + ra * TSTR + 4);
            const float4 A2 = *reinterpret_cast<const float4*>(Ain + ra * TSTR + 8);
            const float4 A3 = *reinterpret_cast<const float4*>(Ain + ra * TSTR + 12);
#pragma unroll
            for (int ib = 0; ib < 8; ++ib) {
                const int b = bpar + 2 * ib;
                const float4 B0 = *reinterpret_cast<const float4*>(Ain + b * TSTR);
                const float4 B1 = *reinterpret_cast<const float4*>(Ain + b * TSTR + 4);
                const float4 B2 = *reinterpret_cast<const float4*>(Ain + b * TSTR + 8);
                const float4 B3 = *reinterpret_cast<const float4*>(Ain + b * TSTR + 12);
                float s = 0.f;
                s = fmaf(A0.x, B0.x, s); s = fmaf(A0.y, B0.y, s);
                s = fmaf(A0.z, B0.z, s); s = fmaf(A0.w, B0.w, s);
                s = fmaf(A1.x, B1.x, s); s = fmaf(A1.y, B1.y, s);
                s = fmaf(A1.z, B1.z, s); s = fmaf(A1.w, B1.w, s);
                s = fmaf(A2.x, B2.x, s); s = fmaf(A2.y, B2.y, s);
                s = fmaf(A2.z, B2.z, s); s = fmaf(A2.w, B2.w, s);
                s = fmaf(A3.x, B3.x, s); s = fmaf(A3.y, B3.y, s);
                s = fmaf(A3.z, B3.z, s); s = fmaf(A3.w, B3.w, s);
                Aou[ra * TSTR + b] = s;
            }
            __syncwarp();
            if (sq == 2) {   // single rescale: keep magnitudes in fp32 range
                float dv = (lane < 16) ? Aou[lane * TSTR + lane] : 0.f;
#pragma unroll
                for (int off = 16; off; off >>= 1)
                    dv = fmaxf(dv, __shfl_xor_sync(FULLM, dv, off));
                float inv = 1.f / fmaxf(dv, 1e-30f);
                for (int e = lane; e < 256; e += 32) {
                    int a = e >> 4, b = e & 15;
                    Aou[a * TSTR + b] *= inv;
                }
                __syncwarp();
            }
            float* tmp = Ain; Ain = Aou; Aou = tmp;
        }

        // dominant eigenvector = largest-diag column, normalized
        float bv = (lane < 16) ? Ain[lane * TSTR + lane] : -1.f;
        int   bx = (lane < 16) ? lane : 1000;
#pragma unroll
        for (int off = 16; off; off >>= 1) {
            float ov = __shfl_xor_sync(FULLM, bv, off);
            int   oi = __shfl_xor_sync(FULLM, bx, off);
            if (ov > bv || (ov == bv && oi < bx)) { bv = ov; bx = oi; }
        }
        float uv = (lane < 16) ? Ain[lane * TSTR + bx] : 0.f;
        float ss = uv * uv;
#pragma unroll
        for (int off = 16; off; off >>= 1) ss += __shfl_xor_sync(FULLM, ss, off);
        float rn = rsqrtf(ss);
        if (lane < 16) uvec[lane] = uv * rn;
        __syncwarp();
    }

    float pd = (lane < 16) ? s_u[w][lane] * s_v[w][lane] : 0.f;
#pragma unroll
    for (int off = 16; off; off >>= 1) pd += __shfl_xor_sync(FULLM, pd, off);
    if (lane == 0) {
        float term = fmaf(-2.f * pd, pd, 2.f);
        atomicAdd(&g_acc_tsa, term);
    }
}

// ---------------- kernel 5: finalize ----------------
__global__ void k_final(float* __restrict__ out) {
    out[0] = g_acc_recon * (1.f / (NB * ND)) + LAMBDA_TSA * g_acc_tsa * (1.f / NB);
}

// ---------------- launcher (kernel launches only; graph-capturable) ----------
extern "C" void kernel_launch(void* const* d_in, const int* in_sizes, int n_in,
                              void* d_out, int out_size) {
    const float* outputs = (const float*)d_in[0];
    const float* targets = (const float*)d_in[1];
    const float* latent  = (const float*)d_in[2];
    const float* raw     = (const float*)d_in[3];
    float* out = (float*)d_out;

    k_setup<<<NB / 256, 256>>>(raw);
    k_recon<<<64, 256>>>(outputs, targets);
    k_knn<<<NB / WPB, 256>>>(raw);
    k_tsa<<<NB / TSA_WPB, 256>>>(latent, raw);
    k_final<<<1, 1>>>(out);
}

// round 11
// speedup vs baseline: 1.1765x; 1.1765x over previous
#include <cuda_runtime.h>
#include <math.h>

#define NB 16384
#define ND 16
#define KNN 25
#define LAMBDA_TSA 0.1f
#define FULLM 0xffffffffu
#define FLTMAX 3.402823466e+38f

#define QPW 2                 // queries per warp
#define WPB 8                 // warps per block
#define QPB (QPW * WPB)       // 16 queries per block
#define CTILE 128             // candidates per smem tile
#define CPAD 20               // padded row stride (16 data + sq + pad); 80B

// ---------------- device scratch (no allocations allowed) ----------------
__device__ float g_sq[NB];
__device__ int   g_nbrs[NB][KNN];
__device__ float g_acc_recon;
__device__ float g_acc_tsa;

// ---------------- kernel 1: squared norms + zero accumulators ----------------
__global__ void k_setup(const float* __restrict__ raw) {
    int i = blockIdx.x * blockDim.x + threadIdx.x;
    if (i < NB) {
        const float4* r4 = reinterpret_cast<const float4*>(raw + (size_t)i * ND);
        float s = 0.f;
#pragma unroll
        for (int j = 0; j < 4; ++j) {
            float4 v = r4[j];
            s = fmaf(v.x, v.x, s); s = fmaf(v.y, v.y, s);
            s = fmaf(v.z, v.z, s); s = fmaf(v.w, v.w, s);
        }
        g_sq[i] = s;
    }
    if (i == 0) { g_acc_recon = 0.f; g_acc_tsa = 0.f; }
}

// ---------------- kernel 2: recon MSE sum ----------------
__global__ void k_recon(const float* __restrict__ o, const float* __restrict__ t) {
    const float4* o4 = reinterpret_cast<const float4*>(o);
    const float4* t4 = reinterpret_cast<const float4*>(t);
    const int n4 = NB * ND / 4;
    float s = 0.f;
    for (int idx = blockIdx.x * blockDim.x + threadIdx.x; idx < n4;
         idx += gridDim.x * blockDim.x) {
        float4 a = o4[idx], b = t4[idx];
        float dx = a.x - b.x, dy = a.y - b.y, dz = a.z - b.z, dw = a.w - b.w;
        s = fmaf(dx, dx, s); s = fmaf(dy, dy, s);
        s = fmaf(dz, dz, s); s = fmaf(dw, dw, s);
    }
#pragma unroll
    for (int off = 16; off; off >>= 1) s += __shfl_xor_sync(FULLM, s, off);
    __shared__ float ws[8];
    int lane = threadIdx.x & 31, wid = threadIdx.x >> 5;
    if (lane == 0) ws[wid] = s;
    __syncthreads();
    if (threadIdx.x == 0) {
        float tot = 0.f;
#pragma unroll
        for (int k = 0; k < 8; ++k) tot += ws[k];
        atomicAdd(&g_acc_recon, tot);
    }
}

// combined max+argmax over list lanes (<KNN); all lanes get the result
__device__ __forceinline__ void maxreduce25(float v, int lane, float& outv, int& outl) {
    float mv = (lane < KNN) ? v : -FLTMAX;
    int   ml = lane;
#pragma unroll
    for (int off = 16; off; off >>= 1) {
        float ov = __shfl_xor_sync(FULLM, mv, off);
        int   ol = __shfl_xor_sync(FULLM, ml, off);
        if (ov > mv || (ov == mv && ol < ml)) { mv = ov; ml = ol; }
    }
    outv = mv; outl = ml;
}

// ---------------- kernel 3: fused distance GEMM + warp-cooperative top-25 ----
// R8 design + double-buffered smem (1 sync/tile). Row-major padded candidate
// tile (80B rows -> conflict-free LDS.128); each lane reads its own candidate
// row (4x LDS.128 + sq in the padding). Distributed top-25, (tau,mlane) state.
__global__ void __launch_bounds__(256) k_knn(const float* __restrict__ raw) {
    __shared__ float Cs[2][CTILE * CPAD];

    const int tid  = threadIdx.x;
    const int lane = tid & 31;
    const int w    = tid >> 5;
    const int qb   = blockIdx.x * QPB + w * QPW;
    const float4* raw4 = reinterpret_cast<const float4*>(raw);

    // per-thread tile-load coordinates (2 float4 per thread per tile)
    const int lc0 = tid >> 2,         ld0 = tid & 3;
    const int lc1 = (tid + 256) >> 2, ld1 = (tid + 256) & 3;

    float qv[QPW][ND];
#pragma unroll
    for (int j = 0; j < QPW; ++j)
#pragma unroll
        for (int d = 0; d < ND; ++d)
            qv[j][d] = __ldg(raw + (size_t)(qb + j) * ND + d);

    float lv[QPW]; int li[QPW]; float tau[QPW]; int mlane[QPW];
#pragma unroll
    for (int j = 0; j < QPW; ++j) { lv[j] = FLTMAX; li[j] = 0; tau[j] = FLTMAX; mlane[j] = 0; }

    // load + store tile 0
    {
        float4 pf0 = raw4[(size_t)lc0 * 4 + ld0];
        float4 pf1 = raw4[(size_t)lc1 * 4 + ld1];
        *reinterpret_cast<float4*>(&Cs[0][lc0 * CPAD + ld0 * 4]) = pf0;
        *reinterpret_cast<float4*>(&Cs[0][lc1 * CPAD + ld1 * 4]) = pf1;
        if (tid < CTILE) Cs[0][tid * CPAD + 16] = g_sq[tid];
    }
    __syncthreads();

    const int NT = NB / CTILE;
    for (int t = 0; t < NT; ++t) {
        const int cbase = t * CTILE;
        const bool more = (t + 1 < NT);

        float4 pf0, pf1; float psq = 0.f;
        if (more) {   // prefetch next tile (LDG latency overlaps compute)
            const int nb4 = (cbase + CTILE) * 4;
            pf0 = raw4[(size_t)nb4 + lc0 * 4 + ld0];
            pf1 = raw4[(size_t)nb4 + lc1 * 4 + ld1];
            if (tid < CTILE) psq = g_sq[cbase + CTILE + tid];
        }
        const float* buf = Cs[t & 1];

#pragma unroll 1
        for (int sub = 0; sub < CTILE / 32; ++sub) {
            const int cloc = sub * 32 + lane;
            const int cg   = cbase + cloc;
            const float4* rp = reinterpret_cast<const float4*>(&buf[cloc * CPAD]);
            const float4 c0 = rp[0], c1 = rp[1], c2 = rp[2], c3 = rp[3];
            const float scv = buf[cloc * CPAD + 16];

            float d2[QPW];
#pragma unroll
            for (int j = 0; j < QPW; ++j) {
                float a = 0.f;
                a = fmaf(qv[j][0],  c0.x, a); a = fmaf(qv[j][1],  c0.y, a);
                a = fmaf(qv[j][2],  c0.z, a); a = fmaf(qv[j][3],  c0.w, a);
                a = fmaf(qv[j][4],  c1.x, a); a = fmaf(qv[j][5],  c1.y, a);
                a = fmaf(qv[j][6],  c1.z, a); a = fmaf(qv[j][7],  c1.w, a);
                a = fmaf(qv[j][8],  c2.x, a); a = fmaf(qv[j][9],  c2.y, a);
                a = fmaf(qv[j][10], c2.z, a); a = fmaf(qv[j][11], c2.w, a);
                a = fmaf(qv[j][12], c3.x, a); a = fmaf(qv[j][13], c3.y, a);
                a = fmaf(qv[j][14], c3.z, a); a = fmaf(qv[j][15], c3.w, a);
                d2[j] = fmaf(-2.f, a, scv);
            }

            if (t == 0 && sub == 0) {
                // seed: lane k's candidate k -> list slot k (self -> FLTMAX hole)
#pragma unroll
                for (int j = 0; j < QPW; ++j) {
                    lv[j] = (lane < KNN && cg != qb + j) ? d2[j] : FLTMAX;
                    li[j] = cg;
                    maxreduce25(lv[j], lane, tau[j], mlane[j]);
                }
                unsigned pb = 0;
#pragma unroll
                for (int j = 0; j < QPW; ++j)
                    if (lane >= KNN && d2[j] < tau[j] && cg != qb + j) pb |= (1u << j);
#pragma unroll
                for (int j = 0; j < QPW; ++j) {
                    unsigned mask = __ballot_sync(FULLM, (pb >> j) & 1u);
                    while (mask) {
                        int src = __ffs(mask) - 1; mask &= mask - 1;
                        float dv = __shfl_sync(FULLM, d2[j], src);
                        int   ci = __shfl_sync(FULLM, cg, src);
                        if (dv < tau[j]) {
                            if (lane == mlane[j]) { lv[j] = dv; li[j] = ci; }
                            maxreduce25(lv[j], lane, tau[j], mlane[j]);
                        }
                    }
                }
                continue;
            }

            unsigned pb = 0;
#pragma unroll
            for (int j = 0; j < QPW; ++j)
                if (d2[j] < tau[j] && cg != qb + j) pb |= (1u << j);
            if (__ballot_sync(FULLM, pb)) {
#pragma unroll
                for (int j = 0; j < QPW; ++j) {
                    unsigned mask = __ballot_sync(FULLM, (pb >> j) & 1u);
                    while (mask) {
                        int src = __ffs(mask) - 1; mask &= mask - 1;
                        float dv = __shfl_sync(FULLM, d2[j], src);
                        int   ci = __shfl_sync(FULLM, cg, src);
                        if (dv < tau[j]) {
                            if (lane == mlane[j]) { lv[j] = dv; li[j] = ci; }
                            maxreduce25(lv[j], lane, tau[j], mlane[j]);
                        }
                    }
                }
            }
        }

        if (more) {   // store next tile into the other buffer (read 2 tiles ago)
            float* nbuf = Cs[(t + 1) & 1];
            *reinterpret_cast<float4*>(&nbuf[lc0 * CPAD + ld0 * 4]) = pf0;
            *reinterpret_cast<float4*>(&nbuf[lc1 * CPAD + ld1 * 4]) = pf1;
            if (tid < CTILE) nbuf[tid * CPAD + 16] = psq;
        }
        __syncthreads();
    }

    if (lane < KNN) {
#pragma unroll
        for (int j = 0; j < QPW; ++j) g_nbrs[qb + j][lane] = li[j];
    }
}

// ---------------- kernel 4: per-point TSA term (warp per point) --------------
// P=1: sum((Pz-Px)^2) = 2 - 2*(u.v)^2, u,v unit top-eigenvectors.
// Eigvec by 7 repeated squarings (A^128), symmetric row-row matmul via
// LDS.128 on stride-20 rows; single mid-way max-diag rescale.
#define TSA_WPB 8
#define TSTR 20
__global__ void __launch_bounds__(256) k_tsa(const float* __restrict__ latent,
                                             const float* __restrict__ raw) {
    __shared__ float s_pts[TSA_WPB][KNN][ND];
    __shared__ float s_A[TSA_WPB][16 * TSTR];
    __shared__ float s_B[TSA_WPB][16 * TSTR];
    __shared__ float s_u[TSA_WPB][16];
    __shared__ float s_v[TSA_WPB][16];
    __shared__ float s_mu[TSA_WPB][16];
    __shared__ int   s_nb[TSA_WPB][KNN];

    const int w = threadIdx.x >> 5, lane = threadIdx.x & 31;
    const int i = blockIdx.x * TSA_WPB + w;
    const int ra   = lane >> 1;     // row a for matmul
    const int bpar = lane & 1;      // b parity

    if (lane < KNN) s_nb[w][lane] = g_nbrs[i][lane];
    __syncwarp();

    for (int p = 0; p < 2; ++p) {
        const float* src = p ? raw : latent;
        float* uvec = p ? s_v[w] : s_u[w];

        for (int idx = lane; idx < KNN * ND; idx += 32) {
            int k = idx >> 4, d = idx & 15;
            s_pts[w][k][d] = src[(size_t)s_nb[w][k] * ND + d];
        }
        __syncwarp();
        if (lane < 16) {
            float m = 0.f;
#pragma unroll
            for (int k = 0; k < KNN; ++k) m += s_pts[w][k][lane];
            s_mu[w][lane] = m * (1.f / KNN);
        }
        __syncwarp();
        for (int idx = lane; idx < KNN * ND; idx += 32) {
            int k = idx >> 4, d = idx & 15;
            s_pts[w][k][d] -= s_mu[w][d];
        }
        __syncwarp();
        // covariance (unnormalized; scale-invariant for eigvec)
        for (int e = lane; e < 256; e += 32) {
            int a = e >> 4, b = e & 15;
            float s = 0.f;
#pragma unroll
            for (int k = 0; k < KNN; ++k) s = fmaf(s_pts[w][k][a], s_pts[w][k][b], s);
            s_A[w][a * TSTR + b] = s;
        }
        __syncwarp();

        float* Ain = s_A[w];
        float* Aou = s_B[w];
#pragma unroll 1
        for (int sq = 0; sq < 7; ++sq) {
            // C[a][b] = row_a . row_b  (A symmetric)
            const float4 A0 = *reinterpret_cast<const float4*>(Ain + ra * TSTR);
            const float4 A1 = *reinterpret_cast<const float4*>(Ain + ra * TSTR + 4);
            const float4 A2 = *reinterpret_cast<const float4*>(Ain + ra * TSTR + 8);
            const float4 A3 = *reinterpret_cast<const float4*>(Ain + ra * TSTR + 12);
#pragma unroll
            for (int ib = 0; ib < 8; ++ib) {
                const int b = bpar + 2 * ib;
                const float4 B0 = *reinterpret_cast<const float4*>(Ain + b * TSTR);
                const float4 B1 = *reinterpret_cast<const float4*>(Ain + b * TSTR + 4);
                const float4 B2 = *reinterpret_cast<const float4*>(Ain + b * TSTR + 8);
                const float4 B3 = *reinterpret_cast<const float4*>(Ain + b * TSTR + 12);
                float s = 0.f;
                s = fmaf(A0.x, B0.x, s); s = fmaf(A0.y, B0.y, s);
                s = fmaf(A0.z, B0.z, s); s = fmaf(A0.w, B0.w, s);
                s = fmaf(A1.x, B1.x, s); s = fmaf(A1.y, B1.y, s);
                s = fmaf(A1.z, B1.z, s); s = fmaf(A1.w, B1.w, s);
                s = fmaf(A2.x, B2.x, s); s = fmaf(A2.y, B2.y, s);
                s = fmaf(A2.z, B2.z, s); s = fmaf(A2.w, B2.w, s);
                s = fmaf(A3.x, B3.x, s); s = fmaf(A3.y, B3.y, s);
                s = fmaf(A3.z, B3.z, s); s = fmaf(A3.w, B3.w, s);
                Aou[ra * TSTR + b] = s;
            }
            __syncwarp();
            if (sq == 2) {   // single rescale: keep magnitudes in fp32 range
                float dv = (lane < 16) ? Aou[lane * TSTR + lane] : 0.f;
#pragma unroll
                for (int off = 16; off; off >>= 1)
                    dv = fmaxf(dv, __shfl_xor_sync(FULLM, dv, off));
                float inv = 1.f / fmaxf(dv, 1e-30f);
                for (int e = lane; e < 256; e += 32) {
                    int a = e >> 4, b = e & 15;
                    Aou[a * TSTR + b] *= inv;
                }
                __syncwarp();
            }
            float* tmp = Ain; Ain = Aou; Aou = tmp;
        }

        // dominant eigenvector = largest-diag column, normalized
        float bv = (lane < 16) ? Ain[lane * TSTR + lane] : -1.f;
        int   bx = (lane < 16) ? lane : 1000;
#pragma unroll
        for (int off = 16; off; off >>= 1) {
            float ov = __shfl_xor_sync(FULLM, bv, off);
            int   oi = __shfl_xor_sync(FULLM, bx, off);
            if (ov > bv || (ov == bv && oi < bx)) { bv = ov; bx = oi; }
        }
        float uv = (lane < 16) ? Ain[lane * TSTR + bx] : 0.f;
        float ss = uv * uv;
#pragma unroll
        for (int off = 16; off; off >>= 1) ss += __shfl_xor_sync(FULLM, ss, off);
        float rn = rsqrtf(ss);
        if (lane < 16) uvec[lane] = uv * rn;
        __syncwarp();
    }

    float pd = (lane < 16) ? s_u[w][lane] * s_v[w][lane] : 0.f;
#pragma unroll
    for (int off = 16; off; off >>= 1) pd += __shfl_xor_sync(FULLM, pd, off);
    if (lane == 0) {
        float term = fmaf(-2.f * pd, pd, 2.f);
        atomicAdd(&g_acc_tsa, term);
    }
}

// ---------------- kernel 5: finalize ----------------
__global__ void k_final(float* __restrict__ out) {
    out[0] = g_acc_recon * (1.f / (NB * ND)) + LAMBDA_TSA * g_acc_tsa * (1.f / NB);
}

// ---------------- launcher (kernel launches only; graph-capturable) ----------
extern "C" void kernel_launch(void* const* d_in, const int* in_sizes, int n_in,
                              void* d_out, int out_size) {
    const float* outputs = (const float*)d_in[0];
    const float* targets = (const float*)d_in[1];
    const float* latent  = (const float*)d_in[2];
    const float* raw     = (const float*)d_in[3];
    float* out = (float*)d_out;

    k_setup<<<NB / 256, 256>>>(raw);
    k_recon<<<64, 256>>>(outputs, targets);
    k_knn<<<NB / QPB, 256>>>(raw);
    k_tsa<<<NB / TSA_WPB, 256>>>(latent, raw);
    k_final<<<1, 1>>>(out);
}